// round 14
// baseline (speedup 1.0000x reference)
#include <cuda_runtime.h>
#include <cuda_fp16.h>

// Problem shape (fixed by the dataset):
//   A: [32, 4096, 64] f32, B: [32, 64, 4096] f32, index: [32, 4096, 32] i32
//   C[b,m,t] = sum_k A[b,m,k] * B[b,k,index[b,m,t]]
#define BB   32
#define MDIM 4096
#define KDIM 64
#define NDIM 4096
#define TOPK 32
#define GRID_PERS 888                    // 148 SMs x 6 blocks
#define TOTAL_M  (BB * MDIM)             // 131072
#define TB       296                     // transpose-producer blocks (first-dispatched)
#define TILES    4096                    // 32 batches x 128 n-tiles (32 n each)
#define TILES_PER_BATCH 128
#define CHUNK_M  4                       // m's per gather ticket (divides 4096)

// 16 MB scratch: transposed B in fp16. Bt16[b][n][k] — one gathered row is
// 64 halves = 128 B = exactly one L1 line (1 wavefront per gather group).
__device__ __half2 g_Bt16[(size_t)BB * NDIM * (KDIM / 2)];

// Progress/work-distribution state (zero-init at load; reset by last block
// each launch -> graph-replay safe).
__device__ unsigned g_cnt[BB];           // completed transpose tiles per batch
__device__ unsigned g_tick;              // gather work ticket (units of CHUNK_M m)
__device__ unsigned g_done;              // blocks finished

__device__ __forceinline__ unsigned ldacq(const unsigned* p) {
    unsigned v;
    asm volatile("ld.acquire.gpu.global.u32 %0, [%1];" : "=r"(v) : "l"(p) : "memory");
    return v;
}

// ---------------------------------------------------------------------------
// Fused kernel. Phase 1 (blocks 0..TB-1): transpose+convert B[b,k,n] f32 ->
// Bt16[b,n,k] fp16 in batch-major interleaved 64k x 32n tiles, publishing
// per-batch completion counters. Phase 2 (all blocks): warp-cooperative
// gather+dot, work distributed by a global ticket in batch order; each warp
// waits (acquire spin) until its chunk's batch is fully transposed. Since
// gather consumes batch b at ~(b/32)*43us and transpose produces it at
// ~(b/32)*9us, waits are cold and the transpose hides under the gather.
// Per-m arithmetic identical to R11 -> bit-identical results.
// grid: 888, block: 256
// ---------------------------------------------------------------------------
__global__ void __launch_bounds__(256) fused_kernel(
    const float* __restrict__ A,
    const float* __restrict__ B,
    const int*   __restrict__ index,
    float*       __restrict__ C)
{
    const int tid = threadIdx.x;

    // ---------------- Phase 1: transpose (first-dispatched blocks only) ----
    if (blockIdx.x < TB) {
        __shared__ float tile[KDIM][33];   // 64 x 33 floats
        for (int t = blockIdx.x; t < TILES; t += TB) {
            const int b  = t >> 7;                 // batch-major order
            const int n0 = (t & 127) * 32;
            const float* Bb = B + (size_t)b * KDIM * NDIM;
            const int tx = tid & 31, ky = tid >> 5;        // 32 n x 8 k threads
            #pragma unroll
            for (int k = ky; k < KDIM; k += 8)
                tile[k][tx] = Bb[(size_t)k * NDIM + n0 + tx];   // coalesced
            __syncthreads();

            const int row = tid >> 3;              // 0..31 (n within tile)
            const int c   = tid & 7;               // 16B chunk: k = 8c..8c+7
            uint4 out;
            __half2* o2 = reinterpret_cast<__half2*>(&out);
            #pragma unroll
            for (int i = 0; i < 4; i++)
                o2[i] = __floats2half2_rn(tile[8 * c + 2 * i][row],
                                          tile[8 * c + 2 * i + 1][row]);
            __half2* dst = g_Bt16 + (size_t)b * NDIM * 32 + (size_t)(n0 + row) * 32;
            reinterpret_cast<uint4*>(dst)[c] = out;

            __threadfence();                        // order STGs before counter
            __syncthreads();                        // also protects smem reuse
            if (tid == 0) atomicAdd(&g_cnt[b], 1u);
        }
    }

    // ---------------- Phase 2: gather + dot (all blocks) -------------------
    const int lane = tid & 31;
    const int j    = lane & 7;
    const int g    = lane >> 3;
    const int t_store = 4 * j + g;                 // bijection on 0..31

    unsigned nxt = 0;
    if (lane == 0) nxt = atomicAdd(&g_tick, CHUNK_M);
    nxt = __shfl_sync(0xffffffffu, nxt, 0);
    int ready_b = -1;

    while (nxt < TOTAL_M) {
        const unsigned mi0 = nxt;
        // prefetch next ticket: atomic latency hides under this chunk's work
        unsigned nn = 0;
        if (lane == 0) nn = atomicAdd(&g_tick, CHUNK_M);
        nxt = __shfl_sync(0xffffffffu, nn, 0);

        const int b = (int)(mi0 >> 12);
        if (b > ready_b) {                          // cold in steady state
            while (ldacq(&g_cnt[b]) < TILES_PER_BATCH) __nanosleep(64);
            ready_b = b;
        }

        const char* BtB = reinterpret_cast<const char*>(
            g_Bt16 + (size_t)b * NDIM * (KDIM / 2));

        #pragma unroll 1
        for (int mm = 0; mm < CHUNK_M; mm++) {
            const int m = (int)(mi0 & (MDIM - 1)) + mm;

            // A row: lane j holds floats [8j, 8j+8), converted to half2 once
            const float4* A4 = reinterpret_cast<const float4*>(
                A + ((size_t)b * MDIM + m) * KDIM);
            const float4 a0 = __ldg(&A4[2 * j]);
            const float4 a1 = __ldg(&A4[2 * j + 1]);
            const __half2 ah0 = __floats2half2_rn(a0.x, a0.y);
            const __half2 ah1 = __floats2half2_rn(a0.z, a0.w);
            const __half2 ah2 = __floats2half2_rn(a1.x, a1.y);
            const __half2 ah3 = __floats2half2_rn(a1.z, a1.w);

            // lane t holds byte offset of row index[t] (pre-scaled)
            const int myoff = __ldg(&index[((size_t)b * MDIM + m) * TOPK + lane]) * 128;

            float p[8];
            #pragma unroll
            for (int i = 0; i < 8; i++) {
                const int offv = __shfl_sync(0xffffffffu, myoff, 4 * i + g);
                // gathered row = 128 B; lane j reads its 16B slice (8 halves)
                const uint4 bv = __ldg(reinterpret_cast<const uint4*>(BtB + offv) + j);

                __half2 acc =       __hmul2(ah0, *reinterpret_cast<const __half2*>(&bv.x));
                acc = __hfma2(ah1, *reinterpret_cast<const __half2*>(&bv.y), acc);
                acc = __hfma2(ah2, *reinterpret_cast<const __half2*>(&bv.z), acc);
                acc = __hfma2(ah3, *reinterpret_cast<const __half2*>(&bv.w), acc);

                const float2 f = __half22float2(acc);
                p[i] = f.x + f.y;
            }

            // Butterfly transpose-reduce (bit-identical tree to R10/R11).
            const int ja = j & 1, jb = (j >> 1) & 1, jc = (j >> 2) & 1;
            float q[4];
            #pragma unroll
            for (int d = 0; d < 4; d++) {
                const float give = ja ? p[2 * d] : p[2 * d + 1];
                const float keep = ja ? p[2 * d + 1] : p[2 * d];
                q[d] = keep + __shfl_xor_sync(0xffffffffu, give, 1);
            }
            float r0, r1;
            {
                const float give0 = jb ? q[0] : q[1];
                const float keep0 = jb ? q[1] : q[0];
                r0 = keep0 + __shfl_xor_sync(0xffffffffu, give0, 2);
                const float give1 = jb ? q[2] : q[3];
                const float keep1 = jb ? q[3] : q[2];
                r1 = keep1 + __shfl_xor_sync(0xffffffffu, give1, 2);
            }
            const float give = jc ? r0 : r1;
            const float keep = jc ? r1 : r0;
            const float total = keep + __shfl_xor_sync(0xffffffffu, give, 4);
            // lane holds i = j  ->  t = 4j + g = t_store

            C[((size_t)b * MDIM + m) * TOPK + t_store] = total;
        }
    }

    // ---------------- Epilogue: last block resets state for graph replay ---
    __syncthreads();
    if (tid == 0) {
        const unsigned d = atomicAdd(&g_done, 1u);
        if (d == GRID_PERS - 1) {
            #pragma unroll
            for (int i = 0; i < BB; i++) g_cnt[i] = 0u;
            g_tick = 0u;
            g_done = 0u;
        }
    }
}

// ---------------------------------------------------------------------------
extern "C" void kernel_launch(void* const* d_in, const int* in_sizes, int n_in,
                              void* d_out, int out_size) {
    const float* A   = (const float*)d_in[0];
    const float* B   = (const float*)d_in[1];
    const int*   idx = (const int*)d_in[2];
    float*       C   = (float*)d_out;

    fused_kernel<<<GRID_PERS, 256>>>(A, B, idx, C);
}

// round 16
// speedup vs baseline: 1.5408x; 1.5408x over previous
#include <cuda_runtime.h>
#include <cuda_fp16.h>

// Problem shape (fixed by the dataset):
//   A: [32, 4096, 64] f32, B: [32, 64, 4096] f32, index: [32, 4096, 32] i32
//   C[b,m,t] = sum_k A[b,m,k] * B[b,k,index[b,m,t]]
#define BB   32
#define MDIM 4096
#define KDIM 64
#define NDIM 4096
#define TOPK 32
#define GRID_PERS 888                    // 148 SMs x 6 blocks (one full wave)
#define NWARPS   (GRID_PERS * 8)         // 7104 persistent warps
#define TOTAL_M  (BB * MDIM)             // 131072
#define TILES    4096                    // 32 batches x 128 n-tiles (32 n each)
#define TILES_PER_BATCH 128

// 16 MB scratch: transposed B in fp16. Bt16[b][n][k] — one gathered row is
// 64 halves = 128 B = exactly one L1 line (1 wavefront per gather group).
__device__ __half2 g_Bt16[(size_t)BB * NDIM * (KDIM / 2)];

// Progress state (zero-init at load; reset by last block -> graph-replay safe).
__device__ unsigned g_cnt[BB];           // completed transpose tiles per batch
__device__ unsigned g_done;              // blocks finished

__device__ __forceinline__ unsigned ldacq(const unsigned* p) {
    unsigned v;
    asm volatile("ld.acquire.gpu.global.u32 %0, [%1];" : "=r"(v) : "l"(p) : "memory");
    return v;
}

// ---------------------------------------------------------------------------
// Fused kernel, fully static schedules (NO work tickets — R14's same-address
// atomic queue serialized the grid).
// Phase 1: all 888 blocks transpose+convert B[b,k,n] f32 -> Bt16[b,n,k] fp16,
// tiles strided batch-major, publishing per-batch counters (spread atomics).
// Phase 2: R11's exact warp-persistent strided gather (mi = w0 + k*7104);
// a warp's batch is monotone, so it gates on g_cnt[b] only when b increments.
// Production of batch b (~(b/32)*9us) far precedes consumption (~(b/32)*43us),
// so gates are cold and the transpose hides under the gather.
// Deadlock-safe: grid = one full co-resident wave (148x6; 40 regs, 8.4KB smem)
// and gates only wait on Phase-1 work that every block performs before its
// own Phase 2 (structure already proven to execute in R14).
// Per-m arithmetic identical to R10/R11 -> bit-identical results.
// grid: 888, block: 256
// ---------------------------------------------------------------------------
__global__ void __launch_bounds__(256) fused_kernel(
    const float* __restrict__ A,
    const float* __restrict__ B,
    const int*   __restrict__ index,
    float*       __restrict__ C)
{
    const int tid = threadIdx.x;

    // ---------------- Phase 1: transpose (static strided, batch-major) ----
    {
        __shared__ float tile[KDIM][33];   // 64 x 33 floats
        for (int t = blockIdx.x; t < TILES; t += GRID_PERS) {
            const int b  = t >> 7;                 // batch-major order
            const int n0 = (t & 127) * 32;
            const float* Bb = B + (size_t)b * KDIM * NDIM;
            const int tx = tid & 31, ky = tid >> 5;        // 32 n x 8 k threads
            #pragma unroll
            for (int k = ky; k < KDIM; k += 8)
                tile[k][tx] = Bb[(size_t)k * NDIM + n0 + tx];   // coalesced
            __syncthreads();

            const int row = tid >> 3;              // 0..31 (n within tile)
            const int c   = tid & 7;               // 16B chunk: k = 8c..8c+7
            uint4 out;
            __half2* o2 = reinterpret_cast<__half2*>(&out);
            #pragma unroll
            for (int i = 0; i < 4; i++)
                o2[i] = __floats2half2_rn(tile[8 * c + 2 * i][row],
                                          tile[8 * c + 2 * i + 1][row]);
            __half2* dst = g_Bt16 + (size_t)b * NDIM * 32 + (size_t)(n0 + row) * 32;
            reinterpret_cast<uint4*>(dst)[c] = out;

            __threadfence();                        // order STGs before counter
            __syncthreads();                        // also protects smem reuse
            if (tid == 0) atomicAdd(&g_cnt[b], 1u); // 32 spread addresses
        }
    }

    // ---------------- Phase 2: gather + dot (R11 static strided) -----------
    const int warp = tid >> 5;
    const int lane = tid & 31;
    const int j    = lane & 7;
    const int g    = lane >> 3;
    const int t_store = 4 * j + g;                 // bijection on 0..31

    const int w0 = blockIdx.x * 8 + warp;          // global warp id
    int ready_b = -1;

    for (int mi = w0; mi < TOTAL_M; mi += NWARPS) {
        const int b = mi >> 12;                    // mi / MDIM (monotone per warp)
        const int m = mi & (MDIM - 1);

        if (b > ready_b) {                          // cold in steady state
            while (ldacq(&g_cnt[b]) < TILES_PER_BATCH) __nanosleep(32);
            ready_b = b;
        }

        const char* BtB = reinterpret_cast<const char*>(
            g_Bt16 + (size_t)b * NDIM * (KDIM / 2));

        // A row: lane j holds floats [8j, 8j+8), converted to half2 once
        const float4* A4 = reinterpret_cast<const float4*>(
            A + ((size_t)b * MDIM + m) * KDIM);
        const float4 a0 = __ldg(&A4[2 * j]);
        const float4 a1 = __ldg(&A4[2 * j + 1]);
        const __half2 ah0 = __floats2half2_rn(a0.x, a0.y);
        const __half2 ah1 = __floats2half2_rn(a0.z, a0.w);
        const __half2 ah2 = __floats2half2_rn(a1.x, a1.y);
        const __half2 ah3 = __floats2half2_rn(a1.z, a1.w);

        // lane t holds byte offset of row index[t] (pre-scaled)
        const int myoff = __ldg(&index[((size_t)b * MDIM + m) * TOPK + lane]) * 128;

        float p[8];
        #pragma unroll
        for (int i = 0; i < 8; i++) {
            const int offv = __shfl_sync(0xffffffffu, myoff, 4 * i + g);
            // gathered row = 128 B; lane j reads its 16B slice (8 halves)
            const uint4 bv = __ldg(reinterpret_cast<const uint4*>(BtB + offv) + j);

            __half2 acc =       __hmul2(ah0, *reinterpret_cast<const __half2*>(&bv.x));
            acc = __hfma2(ah1, *reinterpret_cast<const __half2*>(&bv.y), acc);
            acc = __hfma2(ah2, *reinterpret_cast<const __half2*>(&bv.z), acc);
            acc = __hfma2(ah3, *reinterpret_cast<const __half2*>(&bv.w), acc);

            const float2 f = __half22float2(acc);
            p[i] = f.x + f.y;
        }

        // Butterfly transpose-reduce (bit-identical tree to R10/R11).
        const int ja = j & 1, jb = (j >> 1) & 1, jc = (j >> 2) & 1;
        float q[4];
        #pragma unroll
        for (int d = 0; d < 4; d++) {
            const float give = ja ? p[2 * d] : p[2 * d + 1];
            const float keep = ja ? p[2 * d + 1] : p[2 * d];
            q[d] = keep + __shfl_xor_sync(0xffffffffu, give, 1);
        }
        float r0, r1;
        {
            const float give0 = jb ? q[0] : q[1];
            const float keep0 = jb ? q[1] : q[0];
            r0 = keep0 + __shfl_xor_sync(0xffffffffu, give0, 2);
            const float give1 = jb ? q[2] : q[3];
            const float keep1 = jb ? q[3] : q[2];
            r1 = keep1 + __shfl_xor_sync(0xffffffffu, give1, 2);
        }
        const float give = jc ? r0 : r1;
        const float keep = jc ? r1 : r0;
        const float total = keep + __shfl_xor_sync(0xffffffffu, give, 4);
        // lane holds i = j  ->  t = 4j + g = t_store

        // one 128B line, permuted within line: 1 store wavefront per m
        C[((size_t)b * MDIM + m) * TOPK + t_store] = total;
    }

    // ---------------- Epilogue: last block resets state for graph replay ---
    __syncthreads();
    if (tid == 0) {
        const unsigned d = atomicAdd(&g_done, 1u);
        if (d == GRID_PERS - 1) {
            #pragma unroll
            for (int i = 0; i < BB; i++) g_cnt[i] = 0u;
            g_done = 0u;
        }
    }
}

// ---------------------------------------------------------------------------
extern "C" void kernel_launch(void* const* d_in, const int* in_sizes, int n_in,
                              void* d_out, int out_size) {
    const float* A   = (const float*)d_in[0];
    const float* B   = (const float*)d_in[1];
    const int*   idx = (const int*)d_in[2];
    float*       C   = (float*)d_out;

    fused_kernel<<<GRID_PERS, 256>>>(A, B, idx, C);
}